// round 4
// baseline (speedup 1.0000x reference)
#include <cuda_runtime.h>
#include <math_constants.h>

#define BATCH   32
#define SEQ     8192
#define HID     256
#define NSPLIT  64
#define CHUNK   (SEQ / NSPLIT)        // 128
#define WARPS   8
#define ROWS_PER_IT (WARPS * 2)       // 16 rows per block-iteration
#define ITERS   (CHUNK / ROWS_PER_IT) // 8

// Scratch (allocation-free rule: __device__ globals)
__device__ float g_pm[BATCH * NSPLIT];
__device__ float g_pl[BATCH * NSPLIT];
__device__ float g_pctx[BATCH * NSPLIT * HID];
__device__ float g_M[BATCH];
__device__ float g_L[BATCH];

// Kernel 1: fused score + online softmax + context partials.
// grid (BATCH, NSPLIT), block 256. Each warp processes 2 rows per iteration
// (two independent reduce chains pipelined), 1-deep prefetch of next pair.
__global__ __launch_bounds__(256, 4) void attn_pass1(
    const float* __restrict__ dec,   // (B, H)
    const float* __restrict__ enc,   // (B, S, H)
    float* __restrict__ score_out)   // (B, S) raw scores (normalized later)
{
    const int b     = blockIdx.x;
    const int chunk = blockIdx.y;
    const int tid   = threadIdx.x;
    const int wid   = tid >> 5;
    const int lane  = tid & 31;

    __shared__ float sdec[HID];
    __shared__ float sm[WARPS];
    __shared__ float sl[WARPS];
    __shared__ float sctx[WARPS][HID];

    sdec[tid] = dec[b * HID + tid];
    __syncthreads();

    const float4 d0 = *(const float4*)&sdec[lane * 4];
    const float4 d1 = *(const float4*)&sdec[128 + lane * 4];

    const float* encb = enc + (size_t)b * SEQ * HID + (size_t)chunk * CHUNK * HID;

    float m = -CUDART_INF_F;
    float l = 0.f;
    float c0x = 0.f, c0y = 0.f, c0z = 0.f, c0w = 0.f;
    float c1x = 0.f, c1y = 0.f, c1z = 0.f, c1w = 0.f;

    // prefetch rows for iteration 0: rows (2*wid, 2*wid+1)
    const float* r0 = encb + (size_t)(2 * wid) * HID;
    float4 pA0 = *(const float4*)&r0[lane * 4];
    float4 pA1 = *(const float4*)&r0[128 + lane * 4];
    float4 pB0 = *(const float4*)&r0[HID + lane * 4];
    float4 pB1 = *(const float4*)&r0[HID + 128 + lane * 4];

    #pragma unroll
    for (int it = 0; it < ITERS; ++it) {
        const int s0 = 2 * wid + it * ROWS_PER_IT;   // first of the row pair
        const float4 a0 = pA0, a1 = pA1;             // row s0
        const float4 b0 = pB0, b1 = pB1;             // row s0+1

        if (it + 1 < ITERS) {
            const float* nrow = encb + (size_t)(s0 + ROWS_PER_IT) * HID;
            pA0 = *(const float4*)&nrow[lane * 4];
            pA1 = *(const float4*)&nrow[128 + lane * 4];
            pB0 = *(const float4*)&nrow[HID + lane * 4];
            pB1 = *(const float4*)&nrow[HID + 128 + lane * 4];
        }

        // two independent dot products -> two pipelined shuffle chains
        float pa = a0.x * d0.x + a0.y * d0.y + a0.z * d0.z + a0.w * d0.w
                 + a1.x * d1.x + a1.y * d1.y + a1.z * d1.z + a1.w * d1.w;
        float pb = b0.x * d0.x + b0.y * d0.y + b0.z * d0.z + b0.w * d0.w
                 + b1.x * d1.x + b1.y * d1.y + b1.z * d1.z + b1.w * d1.w;
        #pragma unroll
        for (int o = 16; o; o >>= 1) {
            pa += __shfl_xor_sync(0xffffffffu, pa, o);
            pb += __shfl_xor_sync(0xffffffffu, pb, o);
        }
        const float scoreA = pa;   // warp-uniform
        const float scoreB = pb;

        if (lane == 0) {
            float2 sc = make_float2(scoreA, scoreB);
            *(float2*)&score_out[(size_t)b * SEQ + (size_t)chunk * CHUNK + s0] = sc;
        }

        // online-softmax update with both rows folded in at once
        const float mn = fmaxf(m, fmaxf(scoreA, scoreB));
        const float alpha = __expf(m - mn);
        const float wA    = __expf(scoreA - mn);
        const float wB    = __expf(scoreB - mn);
        l = l * alpha + wA + wB;
        c0x = c0x * alpha + wA * a0.x + wB * b0.x;
        c0y = c0y * alpha + wA * a0.y + wB * b0.y;
        c0z = c0z * alpha + wA * a0.z + wB * b0.z;
        c0w = c0w * alpha + wA * a0.w + wB * b0.w;
        c1x = c1x * alpha + wA * a1.x + wB * b1.x;
        c1y = c1y * alpha + wA * a1.y + wB * b1.y;
        c1z = c1z * alpha + wA * a1.z + wB * b1.z;
        c1w = c1w * alpha + wA * a1.w + wB * b1.w;
        m = mn;
    }

    if (lane == 0) { sm[wid] = m; sl[wid] = l; }
    sctx[wid][lane * 4 + 0] = c0x;  sctx[wid][lane * 4 + 1] = c0y;
    sctx[wid][lane * 4 + 2] = c0z;  sctx[wid][lane * 4 + 3] = c0w;
    sctx[wid][128 + lane * 4 + 0] = c1x;  sctx[wid][128 + lane * 4 + 1] = c1y;
    sctx[wid][128 + lane * 4 + 2] = c1z;  sctx[wid][128 + lane * 4 + 3] = c1w;
    __syncthreads();

    // combine 8 warp partials; each thread owns one h = tid
    float M = sm[0];
    #pragma unroll
    for (int w2 = 1; w2 < WARPS; ++w2) M = fmaxf(M, sm[w2]);
    float L = 0.f, acc = 0.f;
    #pragma unroll
    for (int w2 = 0; w2 < WARPS; ++w2) {
        const float f = __expf(sm[w2] - M);
        L   += f * sl[w2];
        acc += f * sctx[w2][tid];
    }
    const int pidx = b * NSPLIT + chunk;
    if (tid == 0) { g_pm[pidx] = M; g_pl[pidx] = L; }
    g_pctx[(size_t)pidx * HID + tid] = acc;
}

// Kernel 2: combine chunk partials per batch -> context, store (M, L).
__global__ __launch_bounds__(256) void attn_pass2(float* __restrict__ ctx_out)
{
    const int b   = blockIdx.x;
    const int tid = threadIdx.x;

    float M = -CUDART_INF_F;
    #pragma unroll
    for (int k = 0; k < NSPLIT; ++k)
        M = fmaxf(M, g_pm[b * NSPLIT + k]);

    float L = 0.f, acc = 0.f;
    #pragma unroll 8
    for (int k = 0; k < NSPLIT; ++k) {
        const int   pidx = b * NSPLIT + k;
        const float f    = __expf(g_pm[pidx] - M);
        L   += f * g_pl[pidx];
        acc += f * g_pctx[(size_t)pidx * HID + tid];
    }
    ctx_out[b * HID + tid] = acc / L;
    if (tid == 0) { g_M[b] = M; g_L[b] = L; }
}

// Kernel 3: normalize raw scores in place -> atten_prob.
__global__ __launch_bounds__(256) void attn_pass3(float* __restrict__ prob)
{
    const int i = blockIdx.x * blockDim.x + threadIdx.x;  // 0 .. B*S-1
    const int b = i >> 13;                                // / SEQ
    const float inv_l = __frcp_rn(g_L[b]);
    prob[i] = __expf(prob[i] - g_M[b]) * inv_l;
}

extern "C" void kernel_launch(void* const* d_in, const int* in_sizes, int n_in,
                              void* d_out, int out_size)
{
    const float* dec = (const float*)d_in[0];
    const float* enc = (const float*)d_in[1];
    if (n_in >= 2 && in_sizes[0] > in_sizes[1]) {  // defensive: dec is the small one
        const float* t = dec; dec = enc; enc = t;
    }

    float* out       = (float*)d_out;
    float* prob_out  = out;                       // (B, S)
    float* ctx_out   = out + (size_t)BATCH * SEQ; // (B, H)

    dim3 g1(BATCH, NSPLIT);
    attn_pass1<<<g1, 256>>>(dec, enc, prob_out);
    attn_pass2<<<BATCH, 256>>>(ctx_out);
    attn_pass3<<<(BATCH * SEQ) / 256, 256>>>(prob_out);
}

// round 8
// speedup vs baseline: 1.0038x; 1.0038x over previous
#include <cuda_runtime.h>
#include <math_constants.h>

#define BATCH   32
#define SEQ     8192
#define HID     256
#define NSPLIT  64
#define CHUNK   (SEQ / NSPLIT)        // 128
#define WARPS   8
#define ROWS_PER_IT (WARPS * 2)       // 16 rows per block-iteration
#define ITERS   (CHUNK / ROWS_PER_IT) // 8

// Scratch (allocation-free rule: __device__ globals)
__device__ float g_pm[BATCH * NSPLIT];
__device__ float g_pl[BATCH * NSPLIT];
__device__ float g_pctx[BATCH * NSPLIT * HID];

// Kernel 1: fused score + online softmax + context partials.
// grid (BATCH, NSPLIT), block 256. Each warp processes 2 rows per iteration,
// 1-deep prefetch of the next pair.
__global__ __launch_bounds__(256, 4) void attn_pass1(
    const float* __restrict__ dec,   // (B, H)
    const float* __restrict__ enc,   // (B, S, H)
    float* __restrict__ score_out)   // (B, S) raw scores (normalized later)
{
    const int b     = blockIdx.x;
    const int chunk = blockIdx.y;
    const int tid   = threadIdx.x;
    const int wid   = tid >> 5;
    const int lane  = tid & 31;

    __shared__ float sdec[HID];
    __shared__ float sm[WARPS];
    __shared__ float sl[WARPS];
    __shared__ float sctx[WARPS][HID];

    sdec[tid] = dec[b * HID + tid];
    __syncthreads();

    const float4 d0 = *(const float4*)&sdec[lane * 4];
    const float4 d1 = *(const float4*)&sdec[128 + lane * 4];

    const float* encb = enc + (size_t)b * SEQ * HID + (size_t)chunk * CHUNK * HID;

    float m = -CUDART_INF_F;
    float l = 0.f;
    float c0x = 0.f, c0y = 0.f, c0z = 0.f, c0w = 0.f;
    float c1x = 0.f, c1y = 0.f, c1z = 0.f, c1w = 0.f;

    // prefetch rows for iteration 0: rows (2*wid, 2*wid+1)
    const float* r0 = encb + (size_t)(2 * wid) * HID;
    float4 pA0 = *(const float4*)&r0[lane * 4];
    float4 pA1 = *(const float4*)&r0[128 + lane * 4];
    float4 pB0 = *(const float4*)&r0[HID + lane * 4];
    float4 pB1 = *(const float4*)&r0[HID + 128 + lane * 4];

    #pragma unroll
    for (int it = 0; it < ITERS; ++it) {
        const int s0 = 2 * wid + it * ROWS_PER_IT;   // first of the row pair
        const float4 a0 = pA0, a1 = pA1;             // row s0
        const float4 b0 = pB0, b1 = pB1;             // row s0+1

        if (it + 1 < ITERS) {
            const float* nrow = encb + (size_t)(s0 + ROWS_PER_IT) * HID;
            pA0 = *(const float4*)&nrow[lane * 4];
            pA1 = *(const float4*)&nrow[128 + lane * 4];
            pB0 = *(const float4*)&nrow[HID + lane * 4];
            pB1 = *(const float4*)&nrow[HID + 128 + lane * 4];
        }

        // two independent dot products
        float pa = a0.x * d0.x + a0.y * d0.y + a0.z * d0.z + a0.w * d0.w
                 + a1.x * d1.x + a1.y * d1.y + a1.z * d1.z + a1.w * d1.w;
        float pb = b0.x * d0.x + b0.y * d0.y + b0.z * d0.z + b0.w * d0.w
                 + b1.x * d1.x + b1.y * d1.y + b1.z * d1.z + b1.w * d1.w;

        // merged reduction: after the xor-16 step, lower half-warp carries pa,
        // upper half-warp carries pb; 4 butterfly steps finish both at once.
        pa += __shfl_xor_sync(0xffffffffu, pa, 16);
        pb += __shfl_xor_sync(0xffffffffu, pb, 16);
        float t = (lane & 16) ? pb : pa;
        #pragma unroll
        for (int o = 8; o; o >>= 1) t += __shfl_xor_sync(0xffffffffu, t, o);
        const float scoreA = __shfl_sync(0xffffffffu, t, 0);
        const float scoreB = __shfl_sync(0xffffffffu, t, 16);

        if (lane == 0) {
            float2 sc = make_float2(scoreA, scoreB);
            *(float2*)&score_out[(size_t)b * SEQ + (size_t)chunk * CHUNK + s0] = sc;
        }

        // online-softmax update with both rows folded in at once
        const float mn = fmaxf(m, fmaxf(scoreA, scoreB));
        const float alpha = __expf(m - mn);
        const float wA    = __expf(scoreA - mn);
        const float wB    = __expf(scoreB - mn);
        l = l * alpha + wA + wB;
        c0x = c0x * alpha + wA * a0.x + wB * b0.x;
        c0y = c0y * alpha + wA * a0.y + wB * b0.y;
        c0z = c0z * alpha + wA * a0.z + wB * b0.z;
        c0w = c0w * alpha + wA * a0.w + wB * b0.w;
        c1x = c1x * alpha + wA * a1.x + wB * b1.x;
        c1y = c1y * alpha + wA * a1.y + wB * b1.y;
        c1z = c1z * alpha + wA * a1.z + wB * b1.z;
        c1w = c1w * alpha + wA * a1.w + wB * b1.w;
        m = mn;
    }

    if (lane == 0) { sm[wid] = m; sl[wid] = l; }
    sctx[wid][lane * 4 + 0] = c0x;  sctx[wid][lane * 4 + 1] = c0y;
    sctx[wid][lane * 4 + 2] = c0z;  sctx[wid][lane * 4 + 3] = c0w;
    sctx[wid][128 + lane * 4 + 0] = c1x;  sctx[wid][128 + lane * 4 + 1] = c1y;
    sctx[wid][128 + lane * 4 + 2] = c1z;  sctx[wid][128 + lane * 4 + 3] = c1w;
    __syncthreads();

    // combine 8 warp partials; each thread owns one h = tid
    float M = sm[0];
    #pragma unroll
    for (int w2 = 1; w2 < WARPS; ++w2) M = fmaxf(M, sm[w2]);
    float L = 0.f, acc = 0.f;
    #pragma unroll
    for (int w2 = 0; w2 < WARPS; ++w2) {
        const float f = __expf(sm[w2] - M);
        L   += f * sl[w2];
        acc += f * sctx[w2][tid];
    }
    const int pidx = b * NSPLIT + chunk;
    if (tid == 0) { g_pm[pidx] = M; g_pl[pidx] = L; }
    g_pctx[(size_t)pidx * HID + tid] = acc;
}

// Fused epilogue: grid (BATCH, NSPLIT/2), block 256.
// Every block recomputes (M, L) from the 64 chunk partials (L2-resident),
// normalizes 256 scores (two chunks); the y==0 blocks also emit context.
__global__ __launch_bounds__(256) void attn_epilogue(
    float* __restrict__ prob,        // (B, S) raw scores in, probs out
    float* __restrict__ ctx_out)     // (B, H)
{
    const int b   = blockIdx.x;
    const int blk = blockIdx.y;      // 0 .. NSPLIT/2-1
    const int tid = threadIdx.x;

    const float* pm = &g_pm[b * NSPLIT];
    const float* pl = &g_pl[b * NSPLIT];

    float M = -CUDART_INF_F;
    #pragma unroll 8
    for (int k = 0; k < NSPLIT; ++k) M = fmaxf(M, pm[k]);

    float L = 0.f;
    #pragma unroll 8
    for (int k = 0; k < NSPLIT; ++k) L += __expf(pm[k] - M) * pl[k];
    const float inv_l = __frcp_rn(L);

    // normalize two chunks' scores (2*CHUNK = 256 = blockDim)
    const size_t i = (size_t)b * SEQ + (size_t)blk * (2 * CHUNK) + tid;
    prob[i] = __expf(prob[i] - M) * inv_l;

    // first block per batch combines the context partials
    if (blk == 0) {
        float acc = 0.f;
        #pragma unroll 8
        for (int k = 0; k < NSPLIT; ++k) {
            const int pidx = b * NSPLIT + k;
            acc += __expf(g_pm[pidx] - M) * g_pctx[(size_t)pidx * HID + tid];
        }
        ctx_out[b * HID + tid] = acc * inv_l;
    }
}

extern "C" void kernel_launch(void* const* d_in, const int* in_sizes, int n_in,
                              void* d_out, int out_size)
{
    const float* dec = (const float*)d_in[0];
    const float* enc = (const float*)d_in[1];
    if (n_in >= 2 && in_sizes[0] > in_sizes[1]) {  // defensive: dec is the small one
        const float* t = dec; dec = enc; enc = t;
    }

    float* out       = (float*)d_out;
    float* prob_out  = out;                       // (B, S)
    float* ctx_out   = out + (size_t)BATCH * SEQ; // (B, H)

    dim3 g1(BATCH, NSPLIT);
    attn_pass1<<<g1, 256>>>(dec, enc, prob_out);
    dim3 g2(BATCH, NSPLIT / 2);
    attn_epilogue<<<g2, 256>>>(prob_out, ctx_out);
}

// round 9
// speedup vs baseline: 1.0065x; 1.0027x over previous
#include <cuda_runtime.h>
#include <math_constants.h>

#define BATCH   32
#define SEQ     8192
#define HID     256
#define NSPLIT  64
#define CHUNK   (SEQ / NSPLIT)        // 128
#define WARPS   8
#define ROWS_PER_IT (WARPS * 2)       // 16 rows per block-iteration
#define ITERS   (CHUNK / ROWS_PER_IT) // 8

// Scratch (allocation-free rule: __device__ globals)
__device__ float g_pm[BATCH * NSPLIT];
__device__ float g_pl[BATCH * NSPLIT];
__device__ float g_pctx[BATCH * NSPLIT * HID];

// Kernel 1: fused score + online softmax + context partials.
// grid (BATCH, NSPLIT), block 256. Each warp processes 2 rows per iteration,
// 1-deep prefetch of the next pair.
__global__ __launch_bounds__(256, 4) void attn_pass1(
    const float* __restrict__ dec,   // (B, H)
    const float* __restrict__ enc,   // (B, S, H)
    float* __restrict__ score_out)   // (B, S) raw scores (normalized later)
{
    const int b     = blockIdx.x;
    const int chunk = blockIdx.y;
    const int tid   = threadIdx.x;
    const int wid   = tid >> 5;
    const int lane  = tid & 31;

    __shared__ float sdec[HID];
    __shared__ float sm[WARPS];
    __shared__ float sl[WARPS];
    __shared__ float sctx[WARPS][HID];

    sdec[tid] = dec[b * HID + tid];
    __syncthreads();

    const float4 d0 = *(const float4*)&sdec[lane * 4];
    const float4 d1 = *(const float4*)&sdec[128 + lane * 4];

    const float* encb = enc + (size_t)b * SEQ * HID + (size_t)chunk * CHUNK * HID;

    float m = -CUDART_INF_F;
    float l = 0.f;
    float c0x = 0.f, c0y = 0.f, c0z = 0.f, c0w = 0.f;
    float c1x = 0.f, c1y = 0.f, c1z = 0.f, c1w = 0.f;

    // prefetch rows for iteration 0: rows (2*wid, 2*wid+1)
    const float* r0 = encb + (size_t)(2 * wid) * HID;
    float4 pA0 = *(const float4*)&r0[lane * 4];
    float4 pA1 = *(const float4*)&r0[128 + lane * 4];
    float4 pB0 = *(const float4*)&r0[HID + lane * 4];
    float4 pB1 = *(const float4*)&r0[HID + 128 + lane * 4];

    #pragma unroll
    for (int it = 0; it < ITERS; ++it) {
        const int s0 = 2 * wid + it * ROWS_PER_IT;   // first of the row pair
        const float4 a0 = pA0, a1 = pA1;             // row s0
        const float4 b0 = pB0, b1 = pB1;             // row s0+1

        if (it + 1 < ITERS) {
            const float* nrow = encb + (size_t)(s0 + ROWS_PER_IT) * HID;
            pA0 = *(const float4*)&nrow[lane * 4];
            pA1 = *(const float4*)&nrow[128 + lane * 4];
            pB0 = *(const float4*)&nrow[HID + lane * 4];
            pB1 = *(const float4*)&nrow[HID + 128 + lane * 4];
        }

        // two independent dot products
        float pa = a0.x * d0.x + a0.y * d0.y + a0.z * d0.z + a0.w * d0.w
                 + a1.x * d1.x + a1.y * d1.y + a1.z * d1.z + a1.w * d1.w;
        float pb = b0.x * d0.x + b0.y * d0.y + b0.z * d0.z + b0.w * d0.w
                 + b1.x * d1.x + b1.y * d1.y + b1.z * d1.z + b1.w * d1.w;

        // merged reduction: after the xor-16 step, lower half-warp carries pa,
        // upper half-warp carries pb; 4 butterfly steps finish both at once.
        pa += __shfl_xor_sync(0xffffffffu, pa, 16);
        pb += __shfl_xor_sync(0xffffffffu, pb, 16);
        float t = (lane & 16) ? pb : pa;
        #pragma unroll
        for (int o = 8; o; o >>= 1) t += __shfl_xor_sync(0xffffffffu, t, o);
        const float scoreA = __shfl_sync(0xffffffffu, t, 0);
        const float scoreB = __shfl_sync(0xffffffffu, t, 16);

        if (lane == 0) {
            float2 sc = make_float2(scoreA, scoreB);
            *(float2*)&score_out[(size_t)b * SEQ + (size_t)chunk * CHUNK + s0] = sc;
        }

        // online-softmax update with both rows folded in at once
        const float mn = fmaxf(m, fmaxf(scoreA, scoreB));
        const float alpha = __expf(m - mn);
        const float wA    = __expf(scoreA - mn);
        const float wB    = __expf(scoreB - mn);
        l = l * alpha + wA + wB;
        c0x = c0x * alpha + wA * a0.x + wB * b0.x;
        c0y = c0y * alpha + wA * a0.y + wB * b0.y;
        c0z = c0z * alpha + wA * a0.z + wB * b0.z;
        c0w = c0w * alpha + wA * a0.w + wB * b0.w;
        c1x = c1x * alpha + wA * a1.x + wB * b1.x;
        c1y = c1y * alpha + wA * a1.y + wB * b1.y;
        c1z = c1z * alpha + wA * a1.z + wB * b1.z;
        c1w = c1w * alpha + wA * a1.w + wB * b1.w;
        m = mn;
    }

    if (lane == 0) { sm[wid] = m; sl[wid] = l; }
    sctx[wid][lane * 4 + 0] = c0x;  sctx[wid][lane * 4 + 1] = c0y;
    sctx[wid][lane * 4 + 2] = c0z;  sctx[wid][lane * 4 + 3] = c0w;
    sctx[wid][128 + lane * 4 + 0] = c1x;  sctx[wid][128 + lane * 4 + 1] = c1y;
    sctx[wid][128 + lane * 4 + 2] = c1z;  sctx[wid][128 + lane * 4 + 3] = c1w;
    __syncthreads();

    // combine 8 warp partials; each thread owns one h = tid
    float M = sm[0];
    #pragma unroll
    for (int w2 = 1; w2 < WARPS; ++w2) M = fmaxf(M, sm[w2]);
    float L = 0.f, acc = 0.f;
    #pragma unroll
    for (int w2 = 0; w2 < WARPS; ++w2) {
        const float f = __expf(sm[w2] - M);
        L   += f * sl[w2];
        acc += f * sctx[w2][tid];
    }
    const int pidx = b * NSPLIT + chunk;
    if (tid == 0) { g_pm[pidx] = M; g_pl[pidx] = L; }
    g_pctx[(size_t)pidx * HID + tid] = acc;
}

// Kernel 2: finish — one block per batch.
// Computes (M, L) ONCE per batch (expf reused for L and context combine),
// emits context, then normalizes the batch's 8192 scores with float4 loops.
__global__ __launch_bounds__(256) void attn_finish(
    float* __restrict__ prob,        // (B, S) raw scores in, probs out
    float* __restrict__ ctx_out)     // (B, H)
{
    const int b   = blockIdx.x;
    const int tid = threadIdx.x;

    const float* pm = &g_pm[b * NSPLIT];
    const float* pl = &g_pl[b * NSPLIT];

    float M = -CUDART_INF_F;
    #pragma unroll 16
    for (int k = 0; k < NSPLIT; ++k) M = fmaxf(M, pm[k]);

    // single loop: expf factor reused for both L and context accumulation
    float L = 0.f, acc = 0.f;
    #pragma unroll 8
    for (int k = 0; k < NSPLIT; ++k) {
        const float f = __expf(pm[k] - M);
        L   += f * pl[k];
        acc += f * g_pctx[(size_t)(b * NSPLIT + k) * HID + tid];
    }
    const float inv_l = __frcp_rn(L);

    ctx_out[b * HID + tid] = acc * inv_l;

    // normalize this batch's scores: 8192 floats = 2048 float4, 8 per thread
    float4* p = (float4*)(prob + (size_t)b * SEQ);
    #pragma unroll
    for (int i = 0; i < (SEQ / 4) / 256; ++i) {
        float4 v = p[tid + i * 256];
        v.x = __expf(v.x - M) * inv_l;
        v.y = __expf(v.y - M) * inv_l;
        v.z = __expf(v.z - M) * inv_l;
        v.w = __expf(v.w - M) * inv_l;
        p[tid + i * 256] = v;
    }
}

extern "C" void kernel_launch(void* const* d_in, const int* in_sizes, int n_in,
                              void* d_out, int out_size)
{
    const float* dec = (const float*)d_in[0];
    const float* enc = (const float*)d_in[1];
    if (n_in >= 2 && in_sizes[0] > in_sizes[1]) {  // defensive: dec is the small one
        const float* t = dec; dec = enc; enc = t;
    }

    float* out       = (float*)d_out;
    float* prob_out  = out;                       // (B, S)
    float* ctx_out   = out + (size_t)BATCH * SEQ; // (B, H)

    dim3 g1(BATCH, NSPLIT);
    attn_pass1<<<g1, 256>>>(dec, enc, prob_out);
    attn_finish<<<BATCH, 256>>>(prob_out, ctx_out);
}

// round 10
// speedup vs baseline: 1.1291x; 1.1218x over previous
#include <cuda_runtime.h>
#include <math_constants.h>

#define BATCH   32
#define SEQ     8192
#define HID     256
#define NSPLIT  64
#define CHUNK   (SEQ / NSPLIT)        // 128
#define WARPS   8
#define ROWS_PER_IT (WARPS * 2)       // 16 rows per block-iteration
#define ITERS   (CHUNK / ROWS_PER_IT) // 8
#define FIN_Y   8                     // tail blocks per batch

// Scratch (allocation-free rule: __device__ globals)
__device__ float g_pm[BATCH * NSPLIT];
__device__ float g_pl[BATCH * NSPLIT];
__device__ float g_pctx[BATCH * NSPLIT * HID];

// Kernel 1: fused score + online softmax + context partials.
// grid (BATCH, NSPLIT), block 256. Each warp processes 2 rows per iteration,
// 1-deep prefetch of the next pair.  (unchanged: measured ~43us)
__global__ __launch_bounds__(256, 4) void attn_pass1(
    const float* __restrict__ dec,   // (B, H)
    const float* __restrict__ enc,   // (B, S, H)
    float* __restrict__ score_out)   // (B, S) raw scores (normalized later)
{
    const int b     = blockIdx.x;
    const int chunk = blockIdx.y;
    const int tid   = threadIdx.x;
    const int wid   = tid >> 5;
    const int lane  = tid & 31;

    __shared__ float sdec[HID];
    __shared__ float sm[WARPS];
    __shared__ float sl[WARPS];
    __shared__ float sctx[WARPS][HID];

    sdec[tid] = dec[b * HID + tid];
    __syncthreads();

    const float4 d0 = *(const float4*)&sdec[lane * 4];
    const float4 d1 = *(const float4*)&sdec[128 + lane * 4];

    const float* encb = enc + (size_t)b * SEQ * HID + (size_t)chunk * CHUNK * HID;

    float m = -CUDART_INF_F;
    float l = 0.f;
    float c0x = 0.f, c0y = 0.f, c0z = 0.f, c0w = 0.f;
    float c1x = 0.f, c1y = 0.f, c1z = 0.f, c1w = 0.f;

    // prefetch rows for iteration 0: rows (2*wid, 2*wid+1)
    const float* r0 = encb + (size_t)(2 * wid) * HID;
    float4 pA0 = *(const float4*)&r0[lane * 4];
    float4 pA1 = *(const float4*)&r0[128 + lane * 4];
    float4 pB0 = *(const float4*)&r0[HID + lane * 4];
    float4 pB1 = *(const float4*)&r0[HID + 128 + lane * 4];

    #pragma unroll
    for (int it = 0; it < ITERS; ++it) {
        const int s0 = 2 * wid + it * ROWS_PER_IT;   // first of the row pair
        const float4 a0 = pA0, a1 = pA1;             // row s0
        const float4 b0 = pB0, b1 = pB1;             // row s0+1

        if (it + 1 < ITERS) {
            const float* nrow = encb + (size_t)(s0 + ROWS_PER_IT) * HID;
            pA0 = *(const float4*)&nrow[lane * 4];
            pA1 = *(const float4*)&nrow[128 + lane * 4];
            pB0 = *(const float4*)&nrow[HID + lane * 4];
            pB1 = *(const float4*)&nrow[HID + 128 + lane * 4];
        }

        // two independent dot products
        float pa = a0.x * d0.x + a0.y * d0.y + a0.z * d0.z + a0.w * d0.w
                 + a1.x * d1.x + a1.y * d1.y + a1.z * d1.z + a1.w * d1.w;
        float pb = b0.x * d0.x + b0.y * d0.y + b0.z * d0.z + b0.w * d0.w
                 + b1.x * d1.x + b1.y * d1.y + b1.z * d1.z + b1.w * d1.w;

        // merged reduction: after the xor-16 step, lower half-warp carries pa,
        // upper half-warp carries pb; 4 butterfly steps finish both at once.
        pa += __shfl_xor_sync(0xffffffffu, pa, 16);
        pb += __shfl_xor_sync(0xffffffffu, pb, 16);
        float t = (lane & 16) ? pb : pa;
        #pragma unroll
        for (int o = 8; o; o >>= 1) t += __shfl_xor_sync(0xffffffffu, t, o);
        const float scoreA = __shfl_sync(0xffffffffu, t, 0);
        const float scoreB = __shfl_sync(0xffffffffu, t, 16);

        if (lane == 0) {
            float2 sc = make_float2(scoreA, scoreB);
            *(float2*)&score_out[(size_t)b * SEQ + (size_t)chunk * CHUNK + s0] = sc;
        }

        // online-softmax update with both rows folded in at once
        const float mn = fmaxf(m, fmaxf(scoreA, scoreB));
        const float alpha = __expf(m - mn);
        const float wA    = __expf(scoreA - mn);
        const float wB    = __expf(scoreB - mn);
        l = l * alpha + wA + wB;
        c0x = c0x * alpha + wA * a0.x + wB * b0.x;
        c0y = c0y * alpha + wA * a0.y + wB * b0.y;
        c0z = c0z * alpha + wA * a0.z + wB * b0.z;
        c0w = c0w * alpha + wA * a0.w + wB * b0.w;
        c1x = c1x * alpha + wA * a1.x + wB * b1.x;
        c1y = c1y * alpha + wA * a1.y + wB * b1.y;
        c1z = c1z * alpha + wA * a1.z + wB * b1.z;
        c1w = c1w * alpha + wA * a1.w + wB * b1.w;
        m = mn;
    }

    if (lane == 0) { sm[wid] = m; sl[wid] = l; }
    sctx[wid][lane * 4 + 0] = c0x;  sctx[wid][lane * 4 + 1] = c0y;
    sctx[wid][lane * 4 + 2] = c0z;  sctx[wid][lane * 4 + 3] = c0w;
    sctx[wid][128 + lane * 4 + 0] = c1x;  sctx[wid][128 + lane * 4 + 1] = c1y;
    sctx[wid][128 + lane * 4 + 2] = c1z;  sctx[wid][128 + lane * 4 + 3] = c1w;
    __syncthreads();

    // combine 8 warp partials; each thread owns one h = tid
    float M = sm[0];
    #pragma unroll
    for (int w2 = 1; w2 < WARPS; ++w2) M = fmaxf(M, sm[w2]);
    float L = 0.f, acc = 0.f;
    #pragma unroll
    for (int w2 = 0; w2 < WARPS; ++w2) {
        const float f = __expf(sm[w2] - M);
        L   += f * sl[w2];
        acc += f * sctx[w2][tid];
    }
    const int pidx = b * NSPLIT + chunk;
    if (tid == 0) { g_pm[pidx] = M; g_pl[pidx] = L; }
    g_pctx[(size_t)pidx * HID + tid] = acc;
}

// Kernel 2: finish — grid (BATCH, FIN_Y), block 256.
// Parallel (M,L) reduce via threads 0..63; every block normalizes a
// 1024-score slice (1 float4/thread); y==0 blocks also emit context with
// register-staged loads (forced MLP=16).
__global__ __launch_bounds__(256) void attn_finish(
    float* __restrict__ prob,        // (B, S) raw scores in, probs out
    float* __restrict__ ctx_out)     // (B, H)
{
    const int b   = blockIdx.x;
    const int y   = blockIdx.y;
    const int tid = threadIdx.x;
    const int lane = tid & 31;

    __shared__ float sf[NSPLIT];     // expf(pm[k]-M), k = 0..63
    __shared__ float sred[4];        // cross-warp scratch
    __shared__ float sML[2];         // M, inv_l

    // issue the prob float4 load EARLY so it overlaps the (M,L) reduction
    float4* p = (float4*)(prob + (size_t)b * SEQ + (size_t)y * (SEQ / FIN_Y));
    float4 v = p[tid];

    // ---- parallel (M, L): threads 0..63, one chunk each ----
    if (tid < NSPLIT) {
        const float mk = g_pm[b * NSPLIT + tid];
        // max over 64 = butterfly in warp + pair combine in smem
        float mx = mk;
        #pragma unroll
        for (int o = 16; o; o >>= 1) mx = fmaxf(mx, __shfl_xor_sync(0xffffffffu, mx, o));
        if (lane == 0) sred[tid >> 5] = mx;
        __syncwarp();
        // both warps re-read; cheap
    }
    __syncthreads();
    const float M = fmaxf(sred[0], sred[1]);

    if (tid < NSPLIT) {
        const float f = __expf(g_pm[b * NSPLIT + tid] - M);
        sf[tid] = f;
        float fl = f * g_pl[b * NSPLIT + tid];
        #pragma unroll
        for (int o = 16; o; o >>= 1) fl += __shfl_xor_sync(0xffffffffu, fl, o);
        if (lane == 0) sred[2 + (tid >> 5)] = fl;
    }
    __syncthreads();
    if (tid == 0) {
        const float L = sred[2] + sred[3];
        sML[0] = M;
        sML[1] = __frcp_rn(L);
    }
    __syncthreads();
    const float inv_l = sML[1];

    // ---- normalize this block's 1024-score slice ----
    v.x = __expf(v.x - M) * inv_l;
    v.y = __expf(v.y - M) * inv_l;
    v.z = __expf(v.z - M) * inv_l;
    v.w = __expf(v.w - M) * inv_l;
    p[tid] = v;

    // ---- context combine (y == 0 blocks): staged loads, f from smem ----
    if (y == 0) {
        const float* base = &g_pctx[(size_t)(b * NSPLIT) * HID + tid];
        float acc = 0.f;
        #pragma unroll
        for (int g = 0; g < NSPLIT / 16; ++g) {
            float vals[16];
            #pragma unroll
            for (int j = 0; j < 16; ++j)
                vals[j] = base[(size_t)(g * 16 + j) * HID];   // 16 LDGs in flight
            #pragma unroll
            for (int j = 0; j < 16; ++j)
                acc += sf[g * 16 + j] * vals[j];
        }
        ctx_out[b * HID + tid] = acc * inv_l;
    }
}

extern "C" void kernel_launch(void* const* d_in, const int* in_sizes, int n_in,
                              void* d_out, int out_size)
{
    const float* dec = (const float*)d_in[0];
    const float* enc = (const float*)d_in[1];
    if (n_in >= 2 && in_sizes[0] > in_sizes[1]) {  // defensive: dec is the small one
        const float* t = dec; dec = enc; enc = t;
    }

    float* out       = (float*)d_out;
    float* prob_out  = out;                       // (B, S)
    float* ctx_out   = out + (size_t)BATCH * SEQ; // (B, H)

    dim3 g1(BATCH, NSPLIT);
    attn_pass1<<<g1, 256>>>(dec, enc, prob_out);
    dim3 g2(BATCH, FIN_Y);
    attn_finish<<<g2, 256>>>(prob_out, ctx_out);
}